// round 1
// baseline (speedup 1.0000x reference)
#include <cuda_runtime.h>
#include <cstdint>
#include <math.h>

#define WW 512
#define HH 512
#define NB 8
#define NK 8
#define NC 3
#define HW (HH * WW)     /* 262144 */
#define CHW (NC * HW)    /* 786432 */

// output region offsets (float elements), tuple order:
// best_warped[B,C,H,W], best_idx[B], best_mse[B], all_warped_b[B,K,C,H,W], all_mse[B,K], flows[K,H,W,2]
#define OFF_BW   0ull
#define OFF_IDX  6291456ull
#define OFF_BMSE 6291464ull
#define OFF_AW   6291472ull
#define OFF_AMSE 56623120ull
#define OFF_FL   56623184ull

// scratch (device globals -- no allocation allowed)
__device__ float g_sx[NK * HH];          // dx[k][y]  (x-shift, row-constant)
__device__ float g_sy[NK * WW];          // dy[k][x]  (y-shift, col-varying)
__device__ float g_part[NB * NK * HH];   // per-row partial SSE
__device__ float g_mse[NB * NK];
__device__ int   g_best[NB];

__device__ __forceinline__ float softplusf(float x) {
    return fmaxf(x, 0.f) + log1pf(expf(-fabsf(x)));
}

// ---------------- kernel A: shift tables ----------------
__global__ void k_tables(const float* __restrict__ cp) {
    int k = blockIdx.x, t = threadIdx.x;  // t in [0,512)
    float p0 = cp[k * 4 + 0], p1 = cp[k * 4 + 1];
    float p2 = cp[k * 4 + 2], p3 = cp[k * 4 + 3];
    float v_left = 0.5f * tanhf(p0);
    float u_top  = 0.5f * tanhf(p1);
    float decay_x = softplusf(p2);
    float decay_y = softplusf(p3);
    float tc = (float)t * (1.0f / 511.0f);
    g_sx[k * HH + t] = u_top  * expf(-decay_y * tc);  // dx(k, y=t)
    g_sy[k * WW + t] = v_left * expf(-decay_x * tc);  // dy(k, x=t)
}

// ---------------- kernel B: flows output [K,H,W,2] ----------------
__global__ void k_flows(float* __restrict__ out) {
    int y = blockIdx.x, k = blockIdx.y, t = threadIdx.x;  // t in [0,256)
    int x = t * 2;
    float dx = g_sx[k * HH + y];
    float d0 = g_sy[k * WW + x];
    float d1 = g_sy[k * WW + x + 1];
    float4 v = make_float4(dx, d0, dx, d1);
    *reinterpret_cast<float4*>(out + OFF_FL + (((size_t)k * HH + y) * WW + x) * 2) = v;
}

// ---------------- main fused warp + SSE kernel ----------------
// CB: column tap base in 6-wide window (0 => taps x-1,x ; 1 => taps x,x+1)
// RB: row tap base in {ym1,y,yp1}      (0 => rows y-1,y ; 1 => rows y,y+1)
template <int CB, int RB>
__device__ __forceinline__ float warp_body(const float (&nb)[NC][3][6],
                                           const float (&gv)[NC][4],
                                           float wx, const float (&wy)[4],
                                           float* __restrict__ ob) {
    float a = 0.f;
#pragma unroll
    for (int c = 0; c < NC; c++) {
        float ov[4];
#pragma unroll
        for (int j = 0; j < 4; j++) {
            float p00 = nb[c][RB][CB + j],     p01 = nb[c][RB][CB + j + 1];
            float p10 = nb[c][RB + 1][CB + j], p11 = nb[c][RB + 1][CB + j + 1];
            float s0 = fmaf(wx, p01 - p00, p00);
            float s1 = fmaf(wx, p11 - p10, p10);
            float v  = fmaf(wy[j], s1 - s0, s0);
            ov[j] = v;
            float d = v - gv[c][j];
            a = fmaf(d, d, a);
        }
        *reinterpret_cast<float4*>(ob + (size_t)c * HW) =
            make_float4(ov[0], ov[1], ov[2], ov[3]);
    }
    return a;
}

__global__ __launch_bounds__(128) void k_main(const float* __restrict__ pred,
                                              const float* __restrict__ gt,
                                              float* __restrict__ out) {
    const int y = blockIdx.x;
    const int b = blockIdx.y;
    const int t = threadIdx.x;
    const int x0 = t * 4;

    const int ym1 = (y > 0) ? y - 1 : 0;
    const int yp1 = (y < HH - 1) ? y + 1 : HH - 1;
    const int xl = (x0 > 0) ? x0 - 1 : 0;
    const int xr = (x0 + 4 < WW) ? x0 + 4 : WW - 1;
    const int rows[3] = {ym1, y, yp1};

    // 3 channels x 3 rows x 6 cols register neighborhood (clamped halos)
    float nb[NC][3][6];
#pragma unroll
    for (int c = 0; c < NC; c++) {
#pragma unroll
        for (int r = 0; r < 3; r++) {
            const float* pr = pred + ((size_t)(b * NC + c) * HH + rows[r]) * WW;
            nb[c][r][0] = __ldg(pr + xl);
            float4 v = *reinterpret_cast<const float4*>(pr + x0);
            nb[c][r][1] = v.x; nb[c][r][2] = v.y;
            nb[c][r][3] = v.z; nb[c][r][4] = v.w;
            nb[c][r][5] = __ldg(pr + xr);
        }
    }
    float gv[NC][4];
#pragma unroll
    for (int c = 0; c < NC; c++) {
        float4 g4 = *reinterpret_cast<const float4*>(
            gt + ((size_t)(b * NC + c) * HH + y) * WW + x0);
        gv[c][0] = g4.x; gv[c][1] = g4.y; gv[c][2] = g4.z; gv[c][3] = g4.w;
    }

    float acc[NK];
    float* outAW = out + OFF_AW + (size_t)b * NK * CHW + (size_t)y * WW + x0;

#pragma unroll
    for (int k = 0; k < NK; k++) {
        float dxk = g_sx[k * HH + y];          // uniform per block
        float wx = dxk - floorf(dxk);
        float4 dy4 = *reinterpret_cast<const float4*>(g_sy + k * WW + x0);
        float dys[4] = {dy4.x, dy4.y, dy4.z, dy4.w};
        bool yn = dys[0] < 0.f;                // sign uniform along x (exp > 0)
        float of = yn ? -1.f : 0.f;
        float wy[4];
#pragma unroll
        for (int j = 0; j < 4; j++) wy[j] = dys[j] - of;

        float* ob = outAW + (size_t)k * CHW;
        float a;
        if (dxk < 0.f) { a = yn ? warp_body<0, 0>(nb, gv, wx, wy, ob)
                                : warp_body<0, 1>(nb, gv, wx, wy, ob); }
        else           { a = yn ? warp_body<1, 0>(nb, gv, wx, wy, ob)
                                : warp_body<1, 1>(nb, gv, wx, wy, ob); }
        acc[k] = a;
    }

    // deterministic block reduction (no atomics)
    __shared__ float sw[NK][4];
    int lane = t & 31, wid = t >> 5;
#pragma unroll
    for (int k = 0; k < NK; k++) {
        float v = acc[k];
        v += __shfl_down_sync(0xffffffffu, v, 16);
        v += __shfl_down_sync(0xffffffffu, v, 8);
        v += __shfl_down_sync(0xffffffffu, v, 4);
        v += __shfl_down_sync(0xffffffffu, v, 2);
        v += __shfl_down_sync(0xffffffffu, v, 1);
        if (lane == 0) sw[k][wid] = v;
    }
    __syncthreads();
    if (t < NK) {
        float s = sw[t][0] + sw[t][1] + sw[t][2] + sw[t][3];
        g_part[((size_t)b * NK + t) * HH + y] = s;
    }
}

// ---------------- reduce per-row partials -> mse, all_mse ----------------
__global__ void k_reduce(float* __restrict__ out) {
    int id = blockIdx.x;          // b*NK + k
    int t = threadIdx.x;          // 128
    const float* p = g_part + (size_t)id * HH;
    float s = p[t] + p[t + 128] + p[t + 256] + p[t + 384];
    __shared__ float sh[128];
    sh[t] = s;
    __syncthreads();
    for (int o = 64; o > 0; o >>= 1) {
        if (t < o) sh[t] += sh[t + o];
        __syncthreads();
    }
    if (t == 0) {
        float m = sh[0] * (1.0f / (float)CHW);
        g_mse[id] = m;
        out[OFF_AMSE + id] = m;   // all_mse[b,k] (row-major) == id ordering
    }
}

// ---------------- argmin per batch ----------------
__global__ void k_argmin(float* __restrict__ out) {
    int b = threadIdx.x;
    if (b < NB) {
        float bm = g_mse[b * NK];
        int bi = 0;
#pragma unroll
        for (int k = 1; k < NK; k++) {
            float m = g_mse[b * NK + k];
            if (m < bm) { bm = m; bi = k; }   // first-min tiebreak, matches argmin
        }
        g_best[b] = bi;
        out[OFF_IDX + b] = (float)bi;
        out[OFF_BMSE + b] = bm;
    }
}

// ---------------- gather best_warped ----------------
__global__ void k_copy(float* __restrict__ out) {
    size_t i = (size_t)blockIdx.x * blockDim.x + threadIdx.x;  // float4 units
    int b = (int)(i / (CHW / 4));
    size_t r = i - (size_t)b * (CHW / 4);
    int k = g_best[b];
    const float4* src = reinterpret_cast<const float4*>(out) + (OFF_AW / 4) +
                        ((size_t)(b * NK + k)) * (CHW / 4) + r;
    reinterpret_cast<float4*>(out)[i] = *src;
}

extern "C" void kernel_launch(void* const* d_in, const int* in_sizes, int n_in,
                              void* d_out, int out_size) {
    const float* pred = (const float*)d_in[0];
    const float* gt   = (const float*)d_in[1];
    const float* cp   = (const float*)d_in[2];
    float* out = (float*)d_out;
    (void)in_sizes; (void)n_in; (void)out_size;

    k_tables<<<NK, 512>>>(cp);
    k_flows<<<dim3(HH, NK), 256>>>(out);
    k_main<<<dim3(HH, NB), 128>>>(pred, gt, out);
    k_reduce<<<NB * NK, 128>>>(out);
    k_argmin<<<1, 32>>>(out);
    k_copy<<<(NB * CHW / 4) / 256, 256>>>(out);
}

// round 2
// speedup vs baseline: 1.0857x; 1.0857x over previous
#include <cuda_runtime.h>
#include <cstdint>
#include <math.h>

#define WW 512
#define HH 512
#define NB 8
#define NK 8
#define NC 3
#define HW (HH * WW)     /* 262144 */
#define CHW (NC * HW)    /* 786432 */

// output region offsets (float elements), tuple order:
// best_warped[B,C,H,W], best_idx[B], best_mse[B], all_warped_b[B,K,C,H,W], all_mse[B,K], flows[K,H,W,2]
#define OFF_BW   0ull
#define OFF_IDX  6291456ull
#define OFF_BMSE 6291464ull
#define OFF_AW   6291472ull
#define OFF_AMSE 56623120ull
#define OFF_FL   56623184ull

// scratch (device globals -- no allocation allowed)
__device__ float g_sx[NK * HH];          // dx[k][y]  (x-shift, row-constant)
__device__ float g_sy[NK * WW];          // dy[k][x]  (y-shift, col-varying)
__device__ float g_part[NB * NK * HH];   // per-row partial SSE
__device__ int   g_best[NB];

__device__ __forceinline__ float softplusf(float x) {
    return fmaxf(x, 0.f) + log1pf(expf(-fabsf(x)));
}

// ---------------- kernel A: shift tables ----------------
__global__ void k_tables(const float* __restrict__ cp) {
    int k = blockIdx.x, t = threadIdx.x;  // t in [0,512)
    float p0 = cp[k * 4 + 0], p1 = cp[k * 4 + 1];
    float p2 = cp[k * 4 + 2], p3 = cp[k * 4 + 3];
    float v_left = 0.5f * tanhf(p0);
    float u_top  = 0.5f * tanhf(p1);
    float decay_x = softplusf(p2);
    float decay_y = softplusf(p3);
    float tc = (float)t * (1.0f / 511.0f);
    g_sx[k * HH + t] = u_top  * expf(-decay_y * tc);  // dx(k, y=t)
    g_sy[k * WW + t] = v_left * expf(-decay_x * tc);  // dy(k, x=t)
}

// ---------------- main fused warp + SSE (+flows for b==0) kernel ----------------
// CB: column tap base in 6-wide window (0 => taps x-1,x ; 1 => taps x,x+1)
// RB: row tap base in {ym1,y,yp1}      (0 => rows y-1,y ; 1 => rows y,y+1)
template <int CB, int RB>
__device__ __forceinline__ float warp_body(const float (&nb)[NC][3][6],
                                           const float (&gv)[NC][4],
                                           float wx, const float (&wy)[4],
                                           float* __restrict__ ob) {
    float a = 0.f;
#pragma unroll
    for (int c = 0; c < NC; c++) {
        float ov[4];
#pragma unroll
        for (int j = 0; j < 4; j++) {
            float p00 = nb[c][RB][CB + j],     p01 = nb[c][RB][CB + j + 1];
            float p10 = nb[c][RB + 1][CB + j], p11 = nb[c][RB + 1][CB + j + 1];
            float s0 = fmaf(wx, p01 - p00, p00);
            float s1 = fmaf(wx, p11 - p10, p10);
            float v  = fmaf(wy[j], s1 - s0, s0);
            ov[j] = v;
            float d = v - gv[c][j];
            a = fmaf(d, d, a);
        }
        // streaming store: all_warped is write-once, never re-read soon --
        // keep pred/gt resident in L2 instead of thrashing it with 201MB.
        __stcs(reinterpret_cast<float4*>(ob + (size_t)c * HW),
               make_float4(ov[0], ov[1], ov[2], ov[3]));
    }
    return a;
}

__global__ __launch_bounds__(128) void k_main(const float* __restrict__ pred,
                                              const float* __restrict__ gt,
                                              float* __restrict__ out) {
    const int y = blockIdx.x;
    const int b = blockIdx.y;
    const int t = threadIdx.x;
    const int x0 = t * 4;

    const int ym1 = (y > 0) ? y - 1 : 0;
    const int yp1 = (y < HH - 1) ? y + 1 : HH - 1;
    const int xl = (x0 > 0) ? x0 - 1 : 0;
    const int xr = (x0 + 4 < WW) ? x0 + 4 : WW - 1;
    const int rows[3] = {ym1, y, yp1};

    // 3 channels x 3 rows x 6 cols register neighborhood (clamped halos)
    float nb[NC][3][6];
#pragma unroll
    for (int c = 0; c < NC; c++) {
#pragma unroll
        for (int r = 0; r < 3; r++) {
            const float* pr = pred + ((size_t)(b * NC + c) * HH + rows[r]) * WW;
            nb[c][r][0] = __ldg(pr + xl);
            float4 v = *reinterpret_cast<const float4*>(pr + x0);
            nb[c][r][1] = v.x; nb[c][r][2] = v.y;
            nb[c][r][3] = v.z; nb[c][r][4] = v.w;
            nb[c][r][5] = __ldg(pr + xr);
        }
    }
    float gv[NC][4];
#pragma unroll
    for (int c = 0; c < NC; c++) {
        float4 g4 = *reinterpret_cast<const float4*>(
            gt + ((size_t)(b * NC + c) * HH + y) * WW + x0);
        gv[c][0] = g4.x; gv[c][1] = g4.y; gv[c][2] = g4.z; gv[c][3] = g4.w;
    }

    float acc[NK];
    float* outAW = out + OFF_AW + (size_t)b * NK * CHW + (size_t)y * WW + x0;
    const bool do_flows = (b == 0);

#pragma unroll
    for (int k = 0; k < NK; k++) {
        float dxk = g_sx[k * HH + y];          // uniform per block
        float wx = dxk - floorf(dxk);
        float4 dy4 = *reinterpret_cast<const float4*>(g_sy + k * WW + x0);
        float dys[4] = {dy4.x, dy4.y, dy4.z, dy4.w};

        if (do_flows) {   // flows[k,y,x,{dx,dy}] -- piggyback on b==0 blocks
            float* fo = out + OFF_FL + (((size_t)k * HH + y) * WW + x0) * 2;
            __stcs(reinterpret_cast<float4*>(fo),
                   make_float4(dxk, dys[0], dxk, dys[1]));
            __stcs(reinterpret_cast<float4*>(fo + 4),
                   make_float4(dxk, dys[2], dxk, dys[3]));
        }

        bool yn = dys[0] < 0.f;                // sign uniform along x (exp > 0)
        float of = yn ? -1.f : 0.f;
        float wy[4];
#pragma unroll
        for (int j = 0; j < 4; j++) wy[j] = dys[j] - of;

        float* ob = outAW + (size_t)k * CHW;
        float a;
        if (dxk < 0.f) { a = yn ? warp_body<0, 0>(nb, gv, wx, wy, ob)
                                : warp_body<0, 1>(nb, gv, wx, wy, ob); }
        else           { a = yn ? warp_body<1, 0>(nb, gv, wx, wy, ob)
                                : warp_body<1, 1>(nb, gv, wx, wy, ob); }
        acc[k] = a;
    }

    // deterministic block reduction (no atomics)
    __shared__ float sw[NK][4];
    int lane = t & 31, wid = t >> 5;
#pragma unroll
    for (int k = 0; k < NK; k++) {
        float v = acc[k];
        v += __shfl_down_sync(0xffffffffu, v, 16);
        v += __shfl_down_sync(0xffffffffu, v, 8);
        v += __shfl_down_sync(0xffffffffu, v, 4);
        v += __shfl_down_sync(0xffffffffu, v, 2);
        v += __shfl_down_sync(0xffffffffu, v, 1);
        if (lane == 0) sw[k][wid] = v;
    }
    __syncthreads();
    if (t < NK) {
        float s = sw[t][0] + sw[t][1] + sw[t][2] + sw[t][3];
        g_part[((size_t)b * NK + t) * HH + y] = s;
    }
}

// ---------------- fused reduce + argmin: one block per batch ----------------
__global__ void k_finish(float* __restrict__ out) {
    int b = blockIdx.x;
    int t = threadIdx.x;          // 256
    int k = t >> 5, lane = t & 31;
    const float* p = g_part + ((size_t)b * NK + k) * HH;
    float s = 0.f;
#pragma unroll
    for (int i = 0; i < 16; i++) s += p[lane + i * 32];
    s += __shfl_down_sync(0xffffffffu, s, 16);
    s += __shfl_down_sync(0xffffffffu, s, 8);
    s += __shfl_down_sync(0xffffffffu, s, 4);
    s += __shfl_down_sync(0xffffffffu, s, 2);
    s += __shfl_down_sync(0xffffffffu, s, 1);
    __shared__ float sh[NK];
    if (lane == 0) {
        float m = s * (1.0f / (float)CHW);
        sh[k] = m;
        out[OFF_AMSE + b * NK + k] = m;
    }
    __syncthreads();
    if (t == 0) {
        float bm = sh[0];
        int bi = 0;
#pragma unroll
        for (int kk = 1; kk < NK; kk++) {
            float m = sh[kk];
            if (m < bm) { bm = m; bi = kk; }   // first-min tiebreak == argmin
        }
        g_best[b] = bi;
        out[OFF_IDX + b] = (float)bi;
        out[OFF_BMSE + b] = bm;
    }
}

// ---------------- gather best_warped ----------------
__global__ void k_copy(float* __restrict__ out) {
    size_t i = (size_t)blockIdx.x * blockDim.x + threadIdx.x;  // float4 units
    int b = (int)(i / (CHW / 4));
    size_t r = i - (size_t)b * (CHW / 4);
    int k = g_best[b];
    const float4* src = reinterpret_cast<const float4*>(out) + (OFF_AW / 4) +
                        ((size_t)(b * NK + k)) * (CHW / 4) + r;
    float4 v = __ldcs(src);          // read-once: evict-first
    __stcs(reinterpret_cast<float4*>(out) + i, v);  // write-once
}

extern "C" void kernel_launch(void* const* d_in, const int* in_sizes, int n_in,
                              void* d_out, int out_size) {
    const float* pred = (const float*)d_in[0];
    const float* gt   = (const float*)d_in[1];
    const float* cp   = (const float*)d_in[2];
    float* out = (float*)d_out;
    (void)in_sizes; (void)n_in; (void)out_size;

    k_tables<<<NK, 512>>>(cp);
    k_main<<<dim3(HH, NB), 128>>>(pred, gt, out);
    k_finish<<<NB, 256>>>(out);
    k_copy<<<(NB * CHW / 4) / 256, 256>>>(out);
}